// round 15
// baseline (speedup 1.0000x reference)
#include <cuda_runtime.h>
#include <cuda_fp16.h>
#include <cstdint>

#define BATCH 8192
#define INF   4096
#define OUTF  4096

// ---------------- scratch (device globals: no allocs allowed) ----------------
__device__ __half g_Wh[(size_t)OUTF * INF];   // sampled weight, fp16
__device__ __half g_Xh[(size_t)BATCH * INF];  // x, fp16
__device__ float  g_bias[OUTF];               // sampled bias (fp32)

// ---------------- helpers ----------------
__device__ __forceinline__ uint32_t smem_u32(const void* p) {
    return (uint32_t)__cvta_generic_to_shared(p);
}
#define SWZ128(off) ((off) ^ (((off) >> 3) & 0x70))

#define CP_ASYNC16(dst_smem, src_g) \
    asm volatile("cp.async.cg.shared.global [%0], [%1], 16;" :: "r"(dst_smem), "l"(src_g) : "memory")

#define MBARRIER_INIT(addr, cnt) \
    asm volatile("mbarrier.init.shared.b64 [%0], %1;" :: "r"(addr), "r"(cnt) : "memory")

#define MBARRIER_ARRIVE(addr) \
    asm volatile("mbarrier.arrive.shared.b64 _, [%0];" :: "r"(addr) : "memory")

#define CP_ASYNC_ARRIVE_NOINC(addr) \
    asm volatile("cp.async.mbarrier.arrive.noinc.shared.b64 [%0];" :: "r"(addr) : "memory")

#define MBARRIER_WAIT(addr, parity) do {                                             \
    uint32_t _mbar = (addr); uint32_t _par = (parity); uint32_t _done;               \
    asm volatile("{\n\t.reg .pred p;\n\t"                                            \
        "mbarrier.try_wait.parity.shared.b64 p, [%1], %2;\n\t"                       \
        "selp.b32 %0, 1, 0, p;\n\t}"                                                 \
        : "=r"(_done) : "r"(_mbar), "r"(_par) : "memory");                           \
    if (!_done) {                                                                    \
        asm volatile("{\n\t.reg .pred P1;\n\t"                                       \
            "WL_%=:\n\t"                                                             \
            "mbarrier.try_wait.parity.shared.b64 P1, [%0], %1;\n\t"                  \
            "@P1 bra.uni WD_%=;\n\t"                                                 \
            "bra.uni WL_%=;\n\t"                                                     \
            "WD_%=:\n\t}"                                                            \
            :: "r"(_mbar), "r"(_par) : "memory");                                    \
    }                                                                                \
} while (0)

__device__ __forceinline__ void ldm_x4(uint32_t& r0, uint32_t& r1, uint32_t& r2, uint32_t& r3,
                                       uint32_t addr) {
    asm volatile("ldmatrix.sync.aligned.m8n8.x4.shared.b16 {%0,%1,%2,%3}, [%4];"
                 : "=r"(r0), "=r"(r1), "=r"(r2), "=r"(r3) : "r"(addr));
}

__device__ __forceinline__ void mma_f16(float& d0, float& d1, float& d2, float& d3,
                                        uint32_t a0, uint32_t a1, uint32_t a2, uint32_t a3,
                                        uint32_t b0, uint32_t b1) {
    asm volatile("mma.sync.aligned.m16n8k16.row.col.f32.f16.f16.f32 "
                 "{%0,%1,%2,%3}, {%4,%5,%6,%7}, {%8,%9}, {%0,%1,%2,%3};"
                 : "+f"(d0), "+f"(d1), "+f"(d2), "+f"(d3)
                 : "r"(a0), "r"(a1), "r"(a2), "r"(a3), "r"(b0), "r"(b1));
}

__device__ __forceinline__ float softplusf(float r) {
    return (r > 20.0f) ? r : log1pf(__expf(r));
}

// ---------------- fused prologue: sample W + convert X + sample bias ----------------
static constexpr int WBLK = (int)(((size_t)OUTF * INF) / 4 / 256);   // 16384
static constexpr int XBLK = (int)(((size_t)BATCH * INF) / 8 / 256);  // 16384
static constexpr int BBLK = OUTF / 256;                              // 16

__global__ void prologue_kernel(const float* __restrict__ wmu,
                                const float* __restrict__ wrho,
                                const float* __restrict__ weps,
                                const float* __restrict__ x,
                                const float* __restrict__ bmu,
                                const float* __restrict__ brho,
                                const float* __restrict__ beps) {
    const int bid = blockIdx.x;
    if (bid < WBLK) {
        size_t i = ((size_t)bid * blockDim.x + threadIdx.x) * 4;
        float4 m = *reinterpret_cast<const float4*>(wmu + i);
        float4 r = *reinterpret_cast<const float4*>(wrho + i);
        float4 e = *reinterpret_cast<const float4*>(weps + i);
        __half2 lo = __floats2half2_rn(fmaf(softplusf(r.x), e.x, m.x),
                                       fmaf(softplusf(r.y), e.y, m.y));
        __half2 hi = __floats2half2_rn(fmaf(softplusf(r.z), e.z, m.z),
                                       fmaf(softplusf(r.w), e.w, m.w));
        uint2 v;
        v.x = *reinterpret_cast<uint32_t*>(&lo);
        v.y = *reinterpret_cast<uint32_t*>(&hi);
        *reinterpret_cast<uint2*>(g_Wh + i) = v;
    } else if (bid < WBLK + XBLK) {
        size_t i = ((size_t)(bid - WBLK) * blockDim.x + threadIdx.x) * 8;
        float4 v0 = *reinterpret_cast<const float4*>(x + i);
        float4 v1 = *reinterpret_cast<const float4*>(x + i + 4);
        __half2 h0 = __floats2half2_rn(v0.x, v0.y);
        __half2 h1 = __floats2half2_rn(v0.z, v0.w);
        __half2 h2 = __floats2half2_rn(v1.x, v1.y);
        __half2 h3 = __floats2half2_rn(v1.z, v1.w);
        uint4 u;
        u.x = *reinterpret_cast<uint32_t*>(&h0);
        u.y = *reinterpret_cast<uint32_t*>(&h1);
        u.z = *reinterpret_cast<uint32_t*>(&h2);
        u.w = *reinterpret_cast<uint32_t*>(&h3);
        *reinterpret_cast<uint4*>(g_Xh + i) = u;
    } else {
        int i = (bid - WBLK - XBLK) * blockDim.x + threadIdx.x;
        if (i < OUTF) g_bias[i] = fmaf(softplusf(brho[i]), beps[i], bmu[i]);
    }
}

// --- GEMM: 128x128 CTA, 8 warps (64x32 warp tiles), 2 CTAs/SM, fp16 mma,
//     3-stage mbarrier pipeline; empty barriers use lane-0-only arrives (count 8) ---
static constexpr int TILE_M  = 128;
static constexpr int TILE_N  = 128;
static constexpr int KT      = 64;                    // 64 halves = 128B row
static constexpr int NKT     = INF / KT;              // 64
static constexpr int STAGES  = 3;
static constexpr int A_STAGE = TILE_M * 128;          // 16 KB
static constexpr int B_STAGE = TILE_N * 128;          // 16 KB
static constexpr int STAGE_B = A_STAGE + B_STAGE;     // 32 KB
static constexpr int SM_MBAR = STAGES * STAGE_B;      // barriers after stage data
static constexpr int SMEM_B  = SM_MBAR + STAGES * 16; // 96 KB + 48 B

__global__ void __launch_bounds__(256, 2)
bayes_gemm_f16_kernel(float* __restrict__ out) {
    extern __shared__ char smem[];
    const uint32_t sb = smem_u32(smem);
    const int tid  = threadIdx.x;
    const int wid  = tid >> 5, lane = tid & 31;
    const int wm   = wid >> 2;          // 2 warps in M (64 rows each)
    const int wn   = wid & 3;           // 4 warps in N (32 cols each)
    const int m0   = blockIdx.y * TILE_M;
    const int n0   = blockIdx.x * TILE_N;

    // mbarriers: full[s] = sb+SM_MBAR+s*16, empty[s] = +8
    if (tid == 0) {
        #pragma unroll
        for (int s = 0; s < STAGES; s++) {
            MBARRIER_INIT(sb + SM_MBAR + s * 16,     256);  // full: all threads' cp.async
            MBARRIER_INIT(sb + SM_MBAR + s * 16 + 8, 8);    // empty: lane 0 of each warp
        }
    }
    __syncthreads();

    // ---- cp.async geometry: 8 insts/thread/stage (A:4, B:4) ----
    const int prow = tid >> 3;          // 0..31
    const int pc   = tid & 7;           // 16B chunk in 128B row
    const __half* gA = g_Xh + (size_t)(m0 + prow) * INF + pc * 8;
    const __half* gB = g_Wh + (size_t)(n0 + prow) * INF + pc * 8;
    uint32_t offP[4];
    #pragma unroll
    for (int i = 0; i < 4; i++) offP[i] = SWZ128((prow + 32 * i) * 128 + pc * 16);

    auto produce = [&](int k) {
        const int s = k % 3;
        const uint32_t sbase = sb + s * STAGE_B;
        const size_t   koff  = (size_t)k * KT;
        #pragma unroll
        for (int i = 0; i < 4; i++)
            CP_ASYNC16(sbase + offP[i], gA + koff + (size_t)(32 * i) * INF);
        #pragma unroll
        for (int i = 0; i < 4; i++)
            CP_ASYNC16(sbase + A_STAGE + offP[i], gB + koff + (size_t)(32 * i) * INF);
        CP_ASYNC_ARRIVE_NOINC(sb + SM_MBAR + s * 16);   // signal full[s]
    };

    // ---- ldmatrix lane geometry (canonical fp16 m16n8k16 fragments) ----
    const int aRow  = wm * 64 + (lane & 15);
    const int aColB = (lane >> 4) << 4;
    const int bRow  = wn * 32 + (lane & 7) + ((lane >> 4) << 3);
    const int bColB = ((lane >> 3) & 1) << 4;

    float d[4][4][4];
    #pragma unroll
    for (int i = 0; i < 4; i++)
        #pragma unroll
        for (int j = 0; j < 4; j++)
            #pragma unroll
            for (int c = 0; c < 4; c++) d[i][j][c] = 0.0f;

    // ---- prologue: produce ktiles 0,1 (stages 0,1 — first use, no empty wait) ----
    produce(0);
    produce(1);

    for (int kt = 0; kt < NKT; kt++) {
        // produce ktile kt+2 (stage (kt+2)%3)
        const int k = kt + 2;
        if (k < NKT) {
            const int ps = k % 3;
            if (k >= 3) MBARRIER_WAIT(sb + SM_MBAR + ps * 16 + 8, (k / 3 - 1) & 1);
            produce(k);
        }

        // consume ktile kt (stage kt%3)
        const int cs = kt % 3;
        MBARRIER_WAIT(sb + SM_MBAR + cs * 16, (kt / 3) & 1);
        const uint32_t sbase = sb + cs * STAGE_B;

        #pragma unroll
        for (int ks = 0; ks < 4; ks++) {          // 4 x k16
            uint32_t a[4][4], b[2][4];
            #pragma unroll
            for (int i = 0; i < 4; i++) {
                uint32_t addr = sbase + SWZ128((aRow + i * 16) * 128 + aColB + ks * 32);
                ldm_x4(a[i][0], a[i][1], a[i][2], a[i][3], addr);
            }
            #pragma unroll
            for (int jj = 0; jj < 2; jj++) {
                uint32_t addr = sbase + A_STAGE +
                                SWZ128((bRow + jj * 16) * 128 + bColB + ks * 32);
                ldm_x4(b[jj][0], b[jj][1], b[jj][2], b[jj][3], addr);
            }
            #pragma unroll
            for (int i = 0; i < 4; i++)
                #pragma unroll
                for (int j = 0; j < 4; j++)
                    mma_f16(d[i][j][0], d[i][j][1], d[i][j][2], d[i][j][3],
                            a[i][0], a[i][1], a[i][2], a[i][3],
                            b[j >> 1][(j & 1) * 2], b[j >> 1][(j & 1) * 2 + 1]);
        }

        // release stage: ldmatrix is warp-collective, so after the last ldm all
        // lanes' reads are done — a single lane-0 arrive carries the same guarantee
        if (lane == 0) MBARRIER_ARRIVE(sb + SM_MBAR + cs * 16 + 8);
    }

    // ---- epilogue: add bias, store float2 ----
    float2 bv[4];
    #pragma unroll
    for (int j = 0; j < 4; j++)
        bv[j] = *reinterpret_cast<const float2*>(g_bias + n0 + wn * 32 + j * 8 + 2 * (lane & 3));

    #pragma unroll
    for (int i = 0; i < 4; i++) {
        const int r0 = m0 + wm * 64 + i * 16 + (lane >> 2);
        #pragma unroll
        for (int j = 0; j < 4; j++) {
            const int col = n0 + wn * 32 + j * 8 + 2 * (lane & 3);
            float2 v0, v1;
            v0.x = d[i][j][0] + bv[j].x; v0.y = d[i][j][1] + bv[j].y;
            v1.x = d[i][j][2] + bv[j].x; v1.y = d[i][j][3] + bv[j].y;
            *reinterpret_cast<float2*>(out + (size_t)r0 * OUTF + col)       = v0;
            *reinterpret_cast<float2*>(out + (size_t)(r0 + 8) * OUTF + col) = v1;
        }
    }
}

// ---------------- launch ----------------
extern "C" void kernel_launch(void* const* d_in, const int* in_sizes, int n_in,
                              void* d_out, int out_size) {
    const float* x    = (const float*)d_in[0];
    const float* wmu  = (const float*)d_in[1];
    const float* wrho = (const float*)d_in[2];
    const float* bmu  = (const float*)d_in[3];
    const float* brho = (const float*)d_in[4];
    const float* weps = (const float*)d_in[5];
    const float* beps = (const float*)d_in[6];
    float* out = (float*)d_out;

    prologue_kernel<<<WBLK + XBLK + BBLK, 256>>>(wmu, wrho, weps, x, bmu, brho, beps);

    cudaFuncSetAttribute(bayes_gemm_f16_kernel,
                         cudaFuncAttributeMaxDynamicSharedMemorySize, SMEM_B);
    dim3 grid(OUTF / TILE_N, BATCH / TILE_M);  // (32, 64)
    bayes_gemm_f16_kernel<<<grid, 256, SMEM_B>>>(out);
}

// round 16
// speedup vs baseline: 1.5635x; 1.5635x over previous
#include <cuda_runtime.h>
#include <cuda_fp16.h>
#include <cstdint>

#define BATCH 8192
#define INF   4096
#define OUTF  4096

// ---------------- scratch (device globals: no allocs allowed) ----------------
__device__ __half g_Wh[(size_t)OUTF * INF];   // sampled weight, fp16
__device__ __half g_Xh[(size_t)BATCH * INF];  // x, fp16
__device__ float  g_bias[OUTF];               // sampled bias (fp32)

// ---------------- helpers ----------------
__device__ __forceinline__ uint32_t smem_u32(const void* p) {
    return (uint32_t)__cvta_generic_to_shared(p);
}
#define SWZ128(off) ((off) ^ (((off) >> 3) & 0x70))

#define CP_ASYNC16(dst_smem, src_g) \
    asm volatile("cp.async.cg.shared.global [%0], [%1], 16;" :: "r"(dst_smem), "l"(src_g) : "memory")

#define MBARRIER_INIT(addr, cnt) \
    asm volatile("mbarrier.init.shared.b64 [%0], %1;" :: "r"(addr), "r"(cnt) : "memory")

#define MBARRIER_ARRIVE(addr) \
    asm volatile("mbarrier.arrive.shared.b64 _, [%0];" :: "r"(addr) : "memory")

#define CP_ASYNC_ARRIVE_NOINC(addr) \
    asm volatile("cp.async.mbarrier.arrive.noinc.shared.b64 [%0];" :: "r"(addr) : "memory")

#define MBARRIER_WAIT(addr, parity) do {                                             \
    uint32_t _mbar = (addr); uint32_t _par = (parity); uint32_t _done;               \
    asm volatile("{\n\t.reg .pred p;\n\t"                                            \
        "mbarrier.try_wait.parity.shared.b64 p, [%1], %2;\n\t"                       \
        "selp.b32 %0, 1, 0, p;\n\t}"                                                 \
        : "=r"(_done) : "r"(_mbar), "r"(_par) : "memory");                           \
    if (!_done) {                                                                    \
        asm volatile("{\n\t.reg .pred P1;\n\t"                                       \
            "WL_%=:\n\t"                                                             \
            "mbarrier.try_wait.parity.shared.b64 P1, [%0], %1;\n\t"                  \
            "@P1 bra.uni WD_%=;\n\t"                                                 \
            "bra.uni WL_%=;\n\t"                                                     \
            "WD_%=:\n\t}"                                                            \
            :: "r"(_mbar), "r"(_par) : "memory");                                    \
    }                                                                                \
} while (0)

__device__ __forceinline__ void ldm_x4(uint32_t& r0, uint32_t& r1, uint32_t& r2, uint32_t& r3,
                                       uint32_t addr) {
    asm volatile("ldmatrix.sync.aligned.m8n8.x4.shared.b16 {%0,%1,%2,%3}, [%4];"
                 : "=r"(r0), "=r"(r1), "=r"(r2), "=r"(r3) : "r"(addr));
}

__device__ __forceinline__ void mma_f16(float& d0, float& d1, float& d2, float& d3,
                                        uint32_t a0, uint32_t a1, uint32_t a2, uint32_t a3,
                                        uint32_t b0, uint32_t b1) {
    asm volatile("mma.sync.aligned.m16n8k16.row.col.f32.f16.f16.f32 "
                 "{%0,%1,%2,%3}, {%4,%5,%6,%7}, {%8,%9}, {%0,%1,%2,%3};"
                 : "+f"(d0), "+f"(d1), "+f"(d2), "+f"(d3)
                 : "r"(a0), "r"(a1), "r"(a2), "r"(a3), "r"(b0), "r"(b1));
}

__device__ __forceinline__ float softplusf(float r) {
    return (r > 20.0f) ? r : log1pf(__expf(r));
}

// ---------------- fused prologue: sample W + convert X + sample bias ----------------
static constexpr int WBLK = (int)(((size_t)OUTF * INF) / 4 / 256);   // 16384
static constexpr int XBLK = (int)(((size_t)BATCH * INF) / 8 / 256);  // 16384
static constexpr int BBLK = OUTF / 256;                              // 16

__global__ void prologue_kernel(const float* __restrict__ wmu,
                                const float* __restrict__ wrho,
                                const float* __restrict__ weps,
                                const float* __restrict__ x,
                                const float* __restrict__ bmu,
                                const float* __restrict__ brho,
                                const float* __restrict__ beps) {
    const int bid = blockIdx.x;
    if (bid < WBLK) {
        size_t i = ((size_t)bid * blockDim.x + threadIdx.x) * 4;
        float4 m = *reinterpret_cast<const float4*>(wmu + i);
        float4 r = *reinterpret_cast<const float4*>(wrho + i);
        float4 e = *reinterpret_cast<const float4*>(weps + i);
        __half2 lo = __floats2half2_rn(fmaf(softplusf(r.x), e.x, m.x),
                                       fmaf(softplusf(r.y), e.y, m.y));
        __half2 hi = __floats2half2_rn(fmaf(softplusf(r.z), e.z, m.z),
                                       fmaf(softplusf(r.w), e.w, m.w));
        uint2 v;
        v.x = *reinterpret_cast<uint32_t*>(&lo);
        v.y = *reinterpret_cast<uint32_t*>(&hi);
        *reinterpret_cast<uint2*>(g_Wh + i) = v;
    } else if (bid < WBLK + XBLK) {
        size_t i = ((size_t)(bid - WBLK) * blockDim.x + threadIdx.x) * 8;
        float4 v0 = *reinterpret_cast<const float4*>(x + i);
        float4 v1 = *reinterpret_cast<const float4*>(x + i + 4);
        __half2 h0 = __floats2half2_rn(v0.x, v0.y);
        __half2 h1 = __floats2half2_rn(v0.z, v0.w);
        __half2 h2 = __floats2half2_rn(v1.x, v1.y);
        __half2 h3 = __floats2half2_rn(v1.z, v1.w);
        uint4 u;
        u.x = *reinterpret_cast<uint32_t*>(&h0);
        u.y = *reinterpret_cast<uint32_t*>(&h1);
        u.z = *reinterpret_cast<uint32_t*>(&h2);
        u.w = *reinterpret_cast<uint32_t*>(&h3);
        *reinterpret_cast<uint4*>(g_Xh + i) = u;
    } else {
        int i = (bid - WBLK - XBLK) * blockDim.x + threadIdx.x;
        if (i < OUTF) g_bias[i] = fmaf(softplusf(brho[i]), beps[i], bmu[i]);
    }
}

// --- GEMM: 128x128 CTA, 8 warps (64x32 warp tiles), 2 CTAs/SM, fp16 mma,
//     3-stage mbarrier-decoupled pipeline (no block barrier in mainloop) ---
static constexpr int TILE_M  = 128;
static constexpr int TILE_N  = 128;
static constexpr int KT      = 64;                    // 64 halves = 128B row
static constexpr int NKT     = INF / KT;              // 64
static constexpr int STAGES  = 3;
static constexpr int A_STAGE = TILE_M * 128;          // 16 KB
static constexpr int B_STAGE = TILE_N * 128;          // 16 KB
static constexpr int STAGE_B = A_STAGE + B_STAGE;     // 32 KB
static constexpr int SM_MBAR = STAGES * STAGE_B;      // barriers after stage data
static constexpr int SMEM_B  = SM_MBAR + STAGES * 16; // 96 KB + 48 B

__global__ void __launch_bounds__(256, 2)
bayes_gemm_f16_kernel(float* __restrict__ out) {
    extern __shared__ char smem[];
    const uint32_t sb = smem_u32(smem);
    const int tid  = threadIdx.x;
    const int wid  = tid >> 5, lane = tid & 31;
    const int wm   = wid >> 2;          // 2 warps in M (64 rows each)
    const int wn   = wid & 3;           // 4 warps in N (32 cols each)
    const int m0   = blockIdx.y * TILE_M;
    const int n0   = blockIdx.x * TILE_N;

    // mbarriers: full[s] = sb+SM_MBAR+s*16, empty[s] = +8
    if (tid == 0) {
        #pragma unroll
        for (int s = 0; s < STAGES; s++) {
            MBARRIER_INIT(sb + SM_MBAR + s * 16,     256);  // full
            MBARRIER_INIT(sb + SM_MBAR + s * 16 + 8, 256);  // empty
        }
    }
    __syncthreads();

    // ---- cp.async geometry: 8 insts/thread/stage (A:4, B:4) ----
    const int prow = tid >> 3;          // 0..31
    const int pc   = tid & 7;           // 16B chunk in 128B row
    const __half* gA = g_Xh + (size_t)(m0 + prow) * INF + pc * 8;
    const __half* gB = g_Wh + (size_t)(n0 + prow) * INF + pc * 8;
    uint32_t offP[4];
    #pragma unroll
    for (int i = 0; i < 4; i++) offP[i] = SWZ128((prow + 32 * i) * 128 + pc * 16);

    auto produce = [&](int k) {
        const int s = k % 3;
        const uint32_t sbase = sb + s * STAGE_B;
        const size_t   koff  = (size_t)k * KT;
        #pragma unroll
        for (int i = 0; i < 4; i++)
            CP_ASYNC16(sbase + offP[i], gA + koff + (size_t)(32 * i) * INF);
        #pragma unroll
        for (int i = 0; i < 4; i++)
            CP_ASYNC16(sbase + A_STAGE + offP[i], gB + koff + (size_t)(32 * i) * INF);
        CP_ASYNC_ARRIVE_NOINC(sb + SM_MBAR + s * 16);   // signal full[s]
    };

    // ---- ldmatrix lane geometry (canonical fp16 m16n8k16 fragments) ----
    const int aRow  = wm * 64 + (lane & 15);
    const int aColB = (lane >> 4) << 4;
    const int bRow  = wn * 32 + (lane & 7) + ((lane >> 4) << 3);
    const int bColB = ((lane >> 3) & 1) << 4;

    float d[4][4][4];
    #pragma unroll
    for (int i = 0; i < 4; i++)
        #pragma unroll
        for (int j = 0; j < 4; j++)
            #pragma unroll
            for (int c = 0; c < 4; c++) d[i][j][c] = 0.0f;

    // ---- prologue: produce ktiles 0,1 (stages 0,1 — first use, no empty wait) ----
    produce(0);
    produce(1);

    for (int kt = 0; kt < NKT; kt++) {
        // produce ktile kt+2 (stage (kt+2)%3)
        const int k = kt + 2;
        if (k < NKT) {
            const int ps = k % 3;
            if (k >= 3) MBARRIER_WAIT(sb + SM_MBAR + ps * 16 + 8, (k / 3 - 1) & 1);
            produce(k);
        }

        // consume ktile kt (stage kt%3)
        const int cs = kt % 3;
        MBARRIER_WAIT(sb + SM_MBAR + cs * 16, (kt / 3) & 1);
        const uint32_t sbase = sb + cs * STAGE_B;

        #pragma unroll
        for (int ks = 0; ks < 4; ks++) {          // 4 x k16
            uint32_t a[4][4], b[2][4];
            #pragma unroll
            for (int i = 0; i < 4; i++) {
                uint32_t addr = sbase + SWZ128((aRow + i * 16) * 128 + aColB + ks * 32);
                ldm_x4(a[i][0], a[i][1], a[i][2], a[i][3], addr);
            }
            #pragma unroll
            for (int jj = 0; jj < 2; jj++) {
                uint32_t addr = sbase + A_STAGE +
                                SWZ128((bRow + jj * 16) * 128 + bColB + ks * 32);
                ldm_x4(b[jj][0], b[jj][1], b[jj][2], b[jj][3], addr);
            }
            #pragma unroll
            for (int i = 0; i < 4; i++)
                #pragma unroll
                for (int j = 0; j < 4; j++)
                    mma_f16(d[i][j][0], d[i][j][1], d[i][j][2], d[i][j][3],
                            a[i][0], a[i][1], a[i][2], a[i][3],
                            b[j >> 1][(j & 1) * 2], b[j >> 1][(j & 1) * 2 + 1]);
        }

        // release stage for reuse (all 256 threads arrive: per-thread read ordering)
        MBARRIER_ARRIVE(sb + SM_MBAR + cs * 16 + 8);
    }

    // ---- epilogue: add bias, store float2 ----
    float2 bv[4];
    #pragma unroll
    for (int j = 0; j < 4; j++)
        bv[j] = *reinterpret_cast<const float2*>(g_bias + n0 + wn * 32 + j * 8 + 2 * (lane & 3));

    #pragma unroll
    for (int i = 0; i < 4; i++) {
        const int r0 = m0 + wm * 64 + i * 16 + (lane >> 2);
        #pragma unroll
        for (int j = 0; j < 4; j++) {
            const int col = n0 + wn * 32 + j * 8 + 2 * (lane & 3);
            float2 v0, v1;
            v0.x = d[i][j][0] + bv[j].x; v0.y = d[i][j][1] + bv[j].y;
            v1.x = d[i][j][2] + bv[j].x; v1.y = d[i][j][3] + bv[j].y;
            *reinterpret_cast<float2*>(out + (size_t)r0 * OUTF + col)       = v0;
            *reinterpret_cast<float2*>(out + (size_t)(r0 + 8) * OUTF + col) = v1;
        }
    }
}

// ---------------- launch ----------------
extern "C" void kernel_launch(void* const* d_in, const int* in_sizes, int n_in,
                              void* d_out, int out_size) {
    const float* x    = (const float*)d_in[0];
    const float* wmu  = (const float*)d_in[1];
    const float* wrho = (const float*)d_in[2];
    const float* bmu  = (const float*)d_in[3];
    const float* brho = (const float*)d_in[4];
    const float* weps = (const float*)d_in[5];
    const float* beps = (const float*)d_in[6];
    float* out = (float*)d_out;

    prologue_kernel<<<WBLK + XBLK + BBLK, 256>>>(wmu, wrho, weps, x, bmu, brho, beps);

    cudaFuncSetAttribute(bayes_gemm_f16_kernel,
                         cudaFuncAttributeMaxDynamicSharedMemorySize, SMEM_B);
    dim3 grid(OUTF / TILE_N, BATCH / TILE_M);  // (32, 64)
    bayes_gemm_f16_kernel<<<grid, 256, SMEM_B>>>(out);
}